// round 13
// baseline (speedup 1.0000x reference)
#include <cuda_runtime.h>
#include <cuda_bf16.h>
#include <cstdint>

// ---------------- problem constants ----------------
#define N_NODES   100000
#define N_EDGES   1600000
#define NUM_GRAPHS 1024
#define IN_FEAT   7
#define H         128
#define BN_EPS    1e-5f

#define LDP 132   // padded smem row stride (floats)

typedef unsigned long long ull;

// ---------------- scratch (device globals, no allocation) ----------------
__device__ __align__(256) float g_agg[(size_t)N_NODES * H];     // also N x 8 for layer 0
__device__ __align__(256) float g_cat[(size_t)N_NODES * 3 * H];
__device__ __align__(256) float g_pool[(size_t)NUM_GRAPHS * 3 * H];
__device__ __align__(256) float g_hid[(size_t)NUM_GRAPHS * 2 * H];

// ---------------- f32x2 packed-math helpers ----------------
__device__ __forceinline__ void ffma2(ull& d, ull a, ull b) {
    asm("fma.rn.f32x2 %0, %1, %2, %0;" : "+l"(d) : "l"(a), "l"(b));
}
__device__ __forceinline__ ull pkdup(float a) {
    ull r; asm("mov.b64 %0, {%1, %1};" : "=l"(r) : "f"(a)); return r;
}
__device__ __forceinline__ float2 unpk(ull v) {
    float2 r; asm("mov.b64 {%0, %1}, %2;" : "=f"(r.x), "=f"(r.y) : "l"(v)); return r;
}
__device__ __forceinline__ void red_add_v4(float* addr, float4 v) {
    asm volatile("red.global.add.v4.f32 [%0], {%1, %2, %3, %4};"
                 :: "l"(addr), "f"(v.x), "f"(v.y), "f"(v.z), "f"(v.w)
                 : "memory");
}
__device__ __forceinline__ float f4c(const float4& v, int k) {
    return (k == 0) ? v.x : (k == 1) ? v.y : (k == 2) ? v.z : v.w;
}

// ---------------- layer 0: scatter of 7-dim raw features ----------------
__global__ void scatter7_kernel(const float* __restrict__ x,
                                const int* __restrict__ src,
                                const int* __restrict__ dst,
                                float* __restrict__ agg, int E)
{
    int e = blockIdx.x * blockDim.x + threadIdx.x;
    if (e >= E) return;
    int s = src[e];
    int d = dst[e];
    const float* xr = x + (size_t)s * IN_FEAT;
    float* ar = agg + (size_t)d * 8;
    #pragma unroll
    for (int k = 0; k < IN_FEAT; k++) atomicAdd(ar + k, xr[k]);
}

// ---------------- scatter for H=128 features: 4 edges per warp ----------------
__global__ void scatter128_kernel(const float* __restrict__ h, int ldH,
                                  const int* __restrict__ src,
                                  const int* __restrict__ dst,
                                  float* __restrict__ agg, int E)
{
    int warp = (blockIdx.x * blockDim.x + threadIdx.x) >> 5;
    int lane = threadIdx.x & 31;
    int e0 = warp * 4;
    if (e0 >= E) return;

    int s[4], d[4];
    #pragma unroll
    for (int i = 0; i < 4; i++) {
        int e = (e0 + i < E) ? (e0 + i) : (E - 1);
        s[i] = __ldg(src + e);
        d[i] = __ldg(dst + e);
    }
    float4 v[4];
    #pragma unroll
    for (int i = 0; i < 4; i++)
        v[i] = *reinterpret_cast<const float4*>(h + (size_t)s[i] * ldH + lane * 4);
    #pragma unroll
    for (int i = 0; i < 4; i++)
        if (e0 + i < E)
            red_add_v4(agg + (size_t)d[i] * H + lane * 4, v[i]);
}

// ---------------- fused GIN MLP (layers 1,2) ----------------
// Full-A hoist + double-buffered B, f32x2, conflict-free column mapping.
// Thread (tx,ty): rows ty*8..+7, cols {tx*4..+3, 64+tx*4..+3}.
// smem: z_s[128*LDP] (A^T during phase 1, then z row-major) | Bs0[16*LDP] | Bs1[16*LDP]
__global__ void __launch_bounds__(256, 2)
fused_mlp_kernel(const float* __restrict__ A1, int ldA,
                 const float* __restrict__ A2,
                 const float* __restrict__ B1, const float* __restrict__ b1,
                 const float* __restrict__ B2, const float* __restrict__ b2,
                 float* __restrict__ C, int ldC, int N)
{
    extern __shared__ float sm[];
    float* z_s = sm;                      // 128 x LDP
    float* Bs0 = sm + 128 * LDP;          // 16 x LDP
    float* Bs1 = Bs0 + 16 * LDP;          // 16 x LDP

    int tid = threadIdx.x;
    int tx = tid & 15, ty = tid >> 4;
    int m0 = blockIdx.x * 128;

    // ---- stage FULL A = A1 + A2, transposed [k][row], into z_s ----
    for (int kt = 0; kt < H; kt += 16) {
        #pragma unroll
        for (int u = 0; u < 2; u++) {
            int i = tid + u * 256;
            int row = i >> 2;
            int c4 = (i & 3) * 4;
            float4 v = make_float4(0.f, 0.f, 0.f, 0.f);
            int gr = m0 + row;
            if (gr < N) {
                v = *reinterpret_cast<const float4*>(A1 + (size_t)gr * ldA + kt + c4);
                float4 w = *reinterpret_cast<const float4*>(A2 + (size_t)gr * H + kt + c4);
                v.x += w.x; v.y += w.y; v.z += w.z; v.w += w.w;
            }
            z_s[(kt + c4 + 0) * LDP + row] = v.x;
            z_s[(kt + c4 + 1) * LDP + row] = v.y;
            z_s[(kt + c4 + 2) * LDP + row] = v.z;
            z_s[(kt + c4 + 3) * LDP + row] = v.w;
        }
    }
    // stage B1 tile 0 into Bs0
    #pragma unroll
    for (int u = 0; u < 2; u++) {
        int i = tid + u * 256;
        int kr = i >> 5;
        int c4 = (i & 31) * 4;
        *reinterpret_cast<float4*>(&Bs0[kr * LDP + c4]) =
            *reinterpret_cast<const float4*>(B1 + (size_t)kr * H + c4);
    }
    __syncthreads();

    // ---- phase 1: z = relu(A @ B1 + b1), double-buffered B ----
    ull acc[8][4];
    #pragma unroll
    for (int i = 0; i < 8; i++)
        #pragma unroll
        for (int j = 0; j < 4; j++) acc[i][j] = 0ULL;

    #pragma unroll 1
    for (int t = 0; t < 8; t++) {
        float* cur = (t & 1) ? Bs1 : Bs0;
        float* nxt = (t & 1) ? Bs0 : Bs1;
        if (t < 7) {
            int ktn = (t + 1) * 16;
            #pragma unroll
            for (int u = 0; u < 2; u++) {
                int i = tid + u * 256;
                int kr = i >> 5;
                int c4 = (i & 31) * 4;
                *reinterpret_cast<float4*>(&nxt[kr * LDP + c4]) =
                    *reinterpret_cast<const float4*>(B1 + (size_t)(ktn + kr) * H + c4);
            }
        }
        int kb = t * 16;
        #pragma unroll
        for (int k = 0; k < 16; k++) {
            float4 a0 = *reinterpret_cast<const float4*>(&z_s[(kb + k) * LDP + ty * 8]);
            float4 a1 = *reinterpret_cast<const float4*>(&z_s[(kb + k) * LDP + ty * 8 + 4]);
            ulonglong2 bp0 = *reinterpret_cast<const ulonglong2*>(&cur[k * LDP + tx * 4]);
            ulonglong2 bp1 = *reinterpret_cast<const ulonglong2*>(&cur[k * LDP + 64 + tx * 4]);
            ull bb[4] = {bp0.x, bp0.y, bp1.x, bp1.y};
            float av[8] = {a0.x, a0.y, a0.z, a0.w, a1.x, a1.y, a1.z, a1.w};
            ull ad[8];
            #pragma unroll
            for (int i = 0; i < 8; i++) ad[i] = pkdup(av[i]);
            #pragma unroll
            for (int i = 0; i < 8; i++)
                #pragma unroll
                for (int j = 0; j < 4; j++) ffma2(acc[i][j], ad[i], bb[j]);
        }
        __syncthreads();
    }

    // epilogue 1: bias + relu, z -> z_s row-major (A is dead now)
    #pragma unroll
    for (int i = 0; i < 8; i++) {
        int r = ty * 8 + i;
        #pragma unroll
        for (int hlf = 0; hlf < 2; hlf++) {
            int j0 = hlf * 64 + tx * 4;
            float2 p0 = unpk(acc[i][hlf * 2 + 0]);
            float2 p1 = unpk(acc[i][hlf * 2 + 1]);
            float4 o;
            o.x = fmaxf(p0.x + b1[j0 + 0], 0.f);
            o.y = fmaxf(p0.y + b1[j0 + 1], 0.f);
            o.z = fmaxf(p1.x + b1[j0 + 2], 0.f);
            o.w = fmaxf(p1.y + b1[j0 + 3], 0.f);
            *reinterpret_cast<float4*>(&z_s[r * LDP + j0]) = o;
        }
    }
    // stage B2 tile 0 into Bs0 (Bs buffers free)
    #pragma unroll
    for (int u = 0; u < 2; u++) {
        int i = tid + u * 256;
        int kr = i >> 5;
        int c4 = (i & 31) * 4;
        *reinterpret_cast<float4*>(&Bs0[kr * LDP + c4]) =
            *reinterpret_cast<const float4*>(B2 + (size_t)kr * H + c4);
    }
    __syncthreads();

    // ---- phase 2: C = relu(z @ B2 + b2), double-buffered B ----
    ull acc2[8][4];
    #pragma unroll
    for (int i = 0; i < 8; i++)
        #pragma unroll
        for (int j = 0; j < 4; j++) acc2[i][j] = 0ULL;

    #pragma unroll 1
    for (int t = 0; t < 8; t++) {
        float* cur = (t & 1) ? Bs1 : Bs0;
        float* nxt = (t & 1) ? Bs0 : Bs1;
        if (t < 7) {
            int ktn = (t + 1) * 16;
            #pragma unroll
            for (int u = 0; u < 2; u++) {
                int i = tid + u * 256;
                int kr = i >> 5;
                int c4 = (i & 31) * 4;
                *reinterpret_cast<float4*>(&nxt[kr * LDP + c4]) =
                    *reinterpret_cast<const float4*>(B2 + (size_t)(ktn + kr) * H + c4);
            }
        }
        int kb = t * 16;
        #pragma unroll
        for (int kc = 0; kc < 16; kc += 4) {
            float4 rav[8];
            #pragma unroll
            for (int i = 0; i < 8; i++)
                rav[i] = *reinterpret_cast<const float4*>(&z_s[(ty * 8 + i) * LDP + kb + kc]);
            #pragma unroll
            for (int k4 = 0; k4 < 4; k4++) {
                int kr = kc + k4;
                ulonglong2 bp0 = *reinterpret_cast<const ulonglong2*>(&cur[kr * LDP + tx * 4]);
                ulonglong2 bp1 = *reinterpret_cast<const ulonglong2*>(&cur[kr * LDP + 64 + tx * 4]);
                ull bb[4] = {bp0.x, bp0.y, bp1.x, bp1.y};
                ull ad[8];
                #pragma unroll
                for (int i = 0; i < 8; i++) ad[i] = pkdup(f4c(rav[i], k4));
                #pragma unroll
                for (int i = 0; i < 8; i++)
                    #pragma unroll
                    for (int j = 0; j < 4; j++) ffma2(acc2[i][j], ad[i], bb[j]);
            }
        }
        __syncthreads();
    }

    // epilogue 2: bias + relu -> C
    #pragma unroll
    for (int i = 0; i < 8; i++) {
        int gr = m0 + ty * 8 + i;
        if (gr < N) {
            #pragma unroll
            for (int hlf = 0; hlf < 2; hlf++) {
                int j0 = hlf * 64 + tx * 4;
                float2 p0 = unpk(acc2[i][hlf * 2 + 0]);
                float2 p1 = unpk(acc2[i][hlf * 2 + 1]);
                float4 o;
                o.x = fmaxf(p0.x + b2[j0 + 0], 0.f);
                o.y = fmaxf(p0.y + b2[j0 + 1], 0.f);
                o.z = fmaxf(p1.x + b2[j0 + 2], 0.f);
                o.w = fmaxf(p1.y + b2[j0 + 3], 0.f);
                *reinterpret_cast<float4*>(C + (size_t)gr * ldC + j0) = o;
            }
        }
    }
}

// ---------------- fused layer-0 MLP: K1 = 7 (R8-proven) ----------------
// smem: z_s[128*LDP] | in_s[128*8] | Bs[16*LDP]
__global__ void __launch_bounds__(256, 2)
fused_l0_kernel(const float* __restrict__ x,
                const float* __restrict__ agg7,
                const float* __restrict__ B1, const float* __restrict__ b1,
                const float* __restrict__ B2, const float* __restrict__ b2,
                float* __restrict__ C, int ldC, int N)
{
    extern __shared__ float sm[];
    float* z_s  = sm;                     // 128 x LDP
    float* in_s = sm + 128 * LDP;         // 128 x 8
    float* Bs   = in_s + 1024;            // 16 x LDP

    int tid = threadIdx.x;
    int tx = tid & 15, ty = tid >> 4;
    int m0 = blockIdx.x * 128;

    for (int i = tid; i < 128 * IN_FEAT; i += 256) {
        int r = i / IN_FEAT, k = i % IN_FEAT;
        int gr = m0 + r;
        in_s[r * 8 + k] = (gr < N)
            ? x[(size_t)gr * IN_FEAT + k] + agg7[(size_t)gr * 8 + k] : 0.f;
    }
    for (int i = tid; i < IN_FEAT * H; i += 256) {
        int kr = i >> 7, c = i & 127;
        Bs[kr * LDP + c] = B1[i];
    }
    __syncthreads();

    // phase 1: z = relu(in @ B1 + b1)
    ull acc[8][4];
    #pragma unroll
    for (int i = 0; i < 8; i++)
        #pragma unroll
        for (int j = 0; j < 4; j++) acc[i][j] = 0ULL;

    #pragma unroll
    for (int k = 0; k < IN_FEAT; k++) {
        ulonglong2 bp0 = *reinterpret_cast<const ulonglong2*>(&Bs[k * LDP + tx * 4]);
        ulonglong2 bp1 = *reinterpret_cast<const ulonglong2*>(&Bs[k * LDP + 64 + tx * 4]);
        ull bb[4] = {bp0.x, bp0.y, bp1.x, bp1.y};
        ull ad[8];
        #pragma unroll
        for (int i = 0; i < 8; i++) ad[i] = pkdup(in_s[(ty * 8 + i) * 8 + k]);
        #pragma unroll
        for (int i = 0; i < 8; i++)
            #pragma unroll
            for (int j = 0; j < 4; j++) ffma2(acc[i][j], ad[i], bb[j]);
    }

    #pragma unroll
    for (int i = 0; i < 8; i++) {
        int r = ty * 8 + i;
        #pragma unroll
        for (int hlf = 0; hlf < 2; hlf++) {
            int j0 = hlf * 64 + tx * 4;
            float2 p0 = unpk(acc[i][hlf * 2 + 0]);
            float2 p1 = unpk(acc[i][hlf * 2 + 1]);
            float4 o;
            o.x = fmaxf(p0.x + b1[j0 + 0], 0.f);
            o.y = fmaxf(p0.y + b1[j0 + 1], 0.f);
            o.z = fmaxf(p1.x + b1[j0 + 2], 0.f);
            o.w = fmaxf(p1.y + b1[j0 + 3], 0.f);
            *reinterpret_cast<float4*>(&z_s[r * LDP + j0]) = o;
        }
    }
    __syncthreads();   // B1 reads done before Bs overwrite

    // phase 2: C = relu(z @ B2 + b2)
    ull acc2[8][4];
    #pragma unroll
    for (int i = 0; i < 8; i++)
        #pragma unroll
        for (int j = 0; j < 4; j++) acc2[i][j] = 0ULL;

    for (int kt = 0; kt < H; kt += 16) {
        #pragma unroll
        for (int u = 0; u < 2; u++) {
            int i = tid + u * 256;
            int kr = i >> 5;
            int c4 = (i & 31) * 4;
            *reinterpret_cast<float4*>(&Bs[kr * LDP + c4]) =
                *reinterpret_cast<const float4*>(B2 + (size_t)(kt + kr) * H + c4);
        }
        __syncthreads();
        #pragma unroll
        for (int kc = 0; kc < 16; kc += 4) {
            float4 rav[8];
            #pragma unroll
            for (int i = 0; i < 8; i++)
                rav[i] = *reinterpret_cast<const float4*>(&z_s[(ty * 8 + i) * LDP + kt + kc]);
            #pragma unroll
            for (int k4 = 0; k4 < 4; k4++) {
                int kr = kc + k4;
                ulonglong2 bp0 = *reinterpret_cast<const ulonglong2*>(&Bs[kr * LDP + tx * 4]);
                ulonglong2 bp1 = *reinterpret_cast<const ulonglong2*>(&Bs[kr * LDP + 64 + tx * 4]);
                ull bb[4] = {bp0.x, bp0.y, bp1.x, bp1.y};
                ull ad[8];
                #pragma unroll
                for (int i = 0; i < 8; i++) ad[i] = pkdup(f4c(rav[i], k4));
                #pragma unroll
                for (int i = 0; i < 8; i++)
                    #pragma unroll
                    for (int j = 0; j < 4; j++) ffma2(acc2[i][j], ad[i], bb[j]);
            }
        }
        __syncthreads();
    }

    #pragma unroll
    for (int i = 0; i < 8; i++) {
        int gr = m0 + ty * 8 + i;
        if (gr < N) {
            #pragma unroll
            for (int hlf = 0; hlf < 2; hlf++) {
                int j0 = hlf * 64 + tx * 4;
                float2 p0 = unpk(acc2[i][hlf * 2 + 0]);
                float2 p1 = unpk(acc2[i][hlf * 2 + 1]);
                float4 o;
                o.x = fmaxf(p0.x + b2[j0 + 0], 0.f);
                o.y = fmaxf(p0.y + b2[j0 + 1], 0.f);
                o.z = fmaxf(p1.x + b2[j0 + 2], 0.f);
                o.w = fmaxf(p1.y + b2[j0 + 3], 0.f);
                *reinterpret_cast<float4*>(C + (size_t)gr * ldC + j0) = o;
            }
        }
    }
}

// ---------------- global add pool over batch ids ----------------
__global__ void pool_kernel(const float* __restrict__ cat,
                            const int* __restrict__ batch,
                            float* __restrict__ pool, int N)
{
    int t = blockIdx.x * blockDim.x + threadIdx.x;
    int total = N * 96;
    if (t >= total) return;
    int n = t / 96;
    int q = t % 96;
    int g = batch[n];
    float4 v = reinterpret_cast<const float4*>(cat)[(size_t)n * 96 + q];
    red_add_v4(pool + (size_t)g * 384 + q * 4, v);
}

// ---------------- classifier layer 1: 384 -> 256 + BN + relu ----------------
__global__ void clf1_kernel(const float* __restrict__ pool,
                            const float* __restrict__ w,
                            const float* __restrict__ b,
                            const float* __restrict__ gamma,
                            const float* __restrict__ beta,
                            const float* __restrict__ mean,
                            const float* __restrict__ var,
                            float* __restrict__ hid)
{
    __shared__ float sp[384];
    int g = blockIdx.x;
    int j = threadIdx.x;                 // 256
    for (int i = j; i < 384; i += 256) sp[i] = pool[(size_t)g * 384 + i];
    __syncthreads();
    float acc = b[j];
    #pragma unroll 8
    for (int k = 0; k < 384; k++) acc += sp[k] * __ldg(w + (size_t)k * 256 + j);
    acc = (acc - mean[j]) * rsqrtf(var[j] + BN_EPS) * gamma[j] + beta[j];
    hid[(size_t)g * 256 + j] = fmaxf(acc, 0.f);
}

// ---------------- classifier layer 2: 256 -> 2 ----------------
__global__ void clf2_kernel(const float* __restrict__ hid,
                            const float* __restrict__ w,
                            const float* __restrict__ b,
                            float* __restrict__ out)
{
    int t = blockIdx.x * blockDim.x + threadIdx.x;
    if (t >= NUM_GRAPHS * 2) return;
    int g = t >> 1, j = t & 1;
    float acc = b[j];
    const float* hr = hid + (size_t)g * 256;
    #pragma unroll 8
    for (int k = 0; k < 256; k++) acc += hr[k] * __ldg(w + k * 2 + j);
    out[t] = acc;
}

// ---------------- launch ----------------
extern "C" void kernel_launch(void* const* d_in, const int* in_sizes, int n_in,
                              void* d_out, int out_size)
{
    const float* x      = (const float*)d_in[0];
    const int*   ei     = (const int*)d_in[1];
    const int*   batch  = (const int*)d_in[2];
    const float* w1[3], *b1[3], *w2[3], *b2[3];
    for (int l = 0; l < 3; l++) {
        w1[l] = (const float*)d_in[3 + 4 * l + 0];
        b1[l] = (const float*)d_in[3 + 4 * l + 1];
        w2[l] = (const float*)d_in[3 + 4 * l + 2];
        b2[l] = (const float*)d_in[3 + 4 * l + 3];
    }
    const float* clf_w1 = (const float*)d_in[15];
    const float* clf_b1 = (const float*)d_in[16];
    const float* clf_w2 = (const float*)d_in[17];
    const float* clf_b2 = (const float*)d_in[18];
    const float* bn_g   = (const float*)d_in[19];
    const float* bn_b   = (const float*)d_in[20];
    const float* bn_m   = (const float*)d_in[21];
    const float* bn_v   = (const float*)d_in[22];
    float* out = (float*)d_out;

    const int N = in_sizes[0] / IN_FEAT;     // 100000
    const int E = in_sizes[1] / 2;           // 1600000

    float *d_agg, *d_cat, *d_pool, *d_hid;
    cudaGetSymbolAddress((void**)&d_agg, g_agg);
    cudaGetSymbolAddress((void**)&d_cat, g_cat);
    cudaGetSymbolAddress((void**)&d_pool, g_pool);
    cudaGetSymbolAddress((void**)&d_hid, g_hid);

    const int* src = ei;
    const int* dst = ei + E;

    const int gemm_blocks = (N + 127) / 128;
    const int SMEM_MLP = (128 * LDP + 16 * LDP + 16 * LDP) * 4;   // 84480
    const int SMEM_L0  = (128 * LDP + 1024 + 16 * LDP) * 4;       // 80128
    cudaFuncSetAttribute(fused_mlp_kernel, cudaFuncAttributeMaxDynamicSharedMemorySize, SMEM_MLP);
    cudaFuncSetAttribute(fused_l0_kernel,  cudaFuncAttributeMaxDynamicSharedMemorySize, SMEM_L0);

    // ---- layer 0 ----
    cudaMemsetAsync(d_agg, 0, (size_t)N * 8 * sizeof(float));
    scatter7_kernel<<<(E + 255) / 256, 256>>>(x, src, dst, d_agg, E);
    fused_l0_kernel<<<gemm_blocks, 256, SMEM_L0>>>(x, d_agg, w1[0], b1[0],
                                                   w2[0], b2[0], d_cat, 3 * H, N);

    // ---- layers 1, 2 ----
    for (int l = 1; l < 3; l++) {
        const float* h_prev = d_cat + (size_t)(l - 1) * H;  // row stride 384
        cudaMemsetAsync(d_agg, 0, (size_t)N * H * sizeof(float));
        int warps = (E + 3) / 4;
        scatter128_kernel<<<(warps * 32 + 255) / 256, 256>>>(h_prev, 3 * H, src, dst, d_agg, E);
        fused_mlp_kernel<<<gemm_blocks, 256, SMEM_MLP>>>(h_prev, 3 * H, d_agg,
                                                         w1[l], b1[l], w2[l], b2[l],
                                                         d_cat + (size_t)l * H, 3 * H, N);
    }

    // ---- global add pool ----
    cudaMemsetAsync(d_pool, 0, (size_t)NUM_GRAPHS * 384 * sizeof(float));
    pool_kernel<<<(N * 96 + 255) / 256, 256>>>(d_cat, batch, d_pool, N);

    // ---- classifier ----
    clf1_kernel<<<NUM_GRAPHS, 256>>>(d_pool, clf_w1, clf_b1, bn_g, bn_b, bn_m, bn_v, d_hid);
    clf2_kernel<<<(NUM_GRAPHS * 2 + 255) / 256, 256>>>(d_hid, clf_w2, clf_b2, out);
}

// round 14
// speedup vs baseline: 1.5305x; 1.5305x over previous
#include <cuda_runtime.h>
#include <cuda_bf16.h>
#include <cstdint>

// ---------------- problem constants ----------------
#define N_NODES   100000
#define N_EDGES   1600000
#define NUM_GRAPHS 1024
#define IN_FEAT   7
#define H         128
#define BN_EPS    1e-5f

#define LDP 132        // padded stride for l0 kernel (R9-proven)
#define AS_STRIDE 20   // A-tile smem row stride (16 data + 4 pad floats)

typedef unsigned long long ull;

// ---------------- scratch (device globals, no allocation) ----------------
// g_agg padded by 128 rows: last CTA's cp.async reads rows up to 100095.
__device__ __align__(256) float g_agg[(size_t)(N_NODES + 128) * H];
__device__ __align__(256) float g_cat[(size_t)N_NODES * 3 * H];
__device__ __align__(256) float g_pool[(size_t)NUM_GRAPHS * 3 * H];
__device__ __align__(256) float g_hid[(size_t)NUM_GRAPHS * 2 * H];

// ---------------- helpers ----------------
__device__ __forceinline__ void ffma2(ull& d, ull a, ull b) {
    asm("fma.rn.f32x2 %0, %1, %2, %0;" : "+l"(d) : "l"(a), "l"(b));
}
__device__ __forceinline__ ull pkdup(float a) {
    ull r; asm("mov.b64 %0, {%1, %1};" : "=l"(r) : "f"(a)); return r;
}
__device__ __forceinline__ float2 unpk(ull v) {
    float2 r; asm("mov.b64 {%0, %1}, %2;" : "=f"(r.x), "=f"(r.y) : "l"(v)); return r;
}
__device__ __forceinline__ void red_add_v4(float* addr, float4 v) {
    asm volatile("red.global.add.v4.f32 [%0], {%1, %2, %3, %4};"
                 :: "l"(addr), "f"(v.x), "f"(v.y), "f"(v.z), "f"(v.w)
                 : "memory");
}
__device__ __forceinline__ float f4c(const float4& v, int k) {
    return (k == 0) ? v.x : (k == 1) ? v.y : (k == 2) ? v.z : v.w;
}
__device__ __forceinline__ uint32_t smem_to_u32(const void* p) {
    uint32_t a;
    asm("{ .reg .u64 t; cvta.to.shared.u64 t, %1; cvt.u32.u64 %0, t; }" : "=r"(a) : "l"(p));
    return a;
}
__device__ __forceinline__ void cpa16(uint32_t d, const float* s) {
    asm volatile("cp.async.cg.shared.global [%0], [%1], 16;" :: "r"(d), "l"(s));
}
#define CP_COMMIT() asm volatile("cp.async.commit_group;" ::: "memory")
#define CP_WAIT0()  asm volatile("cp.async.wait_group 0;" ::: "memory")

// ---------------- layer 0: scatter of 7-dim raw features ----------------
__global__ void scatter7_kernel(const float* __restrict__ x,
                                const int* __restrict__ src,
                                const int* __restrict__ dst,
                                float* __restrict__ agg, int E)
{
    int e = blockIdx.x * blockDim.x + threadIdx.x;
    if (e >= E) return;
    int s = src[e];
    int d = dst[e];
    const float* xr = x + (size_t)s * IN_FEAT;
    float* ar = agg + (size_t)d * 8;
    #pragma unroll
    for (int k = 0; k < IN_FEAT; k++) atomicAdd(ar + k, xr[k]);
}

// ---------------- scatter for H=128 features: 4 edges per warp ----------------
__global__ void scatter128_kernel(const float* __restrict__ h, int ldH,
                                  const int* __restrict__ src,
                                  const int* __restrict__ dst,
                                  float* __restrict__ agg, int E)
{
    int warp = (blockIdx.x * blockDim.x + threadIdx.x) >> 5;
    int lane = threadIdx.x & 31;
    int e0 = warp * 4;
    if (e0 >= E) return;

    int s[4], d[4];
    #pragma unroll
    for (int i = 0; i < 4; i++) {
        int e = (e0 + i < E) ? (e0 + i) : (E - 1);
        s[i] = __ldg(src + e);
        d[i] = __ldg(dst + e);
    }
    float4 v[4];
    #pragma unroll
    for (int i = 0; i < 4; i++)
        v[i] = *reinterpret_cast<const float4*>(h + (size_t)s[i] * ldH + lane * 4);
    #pragma unroll
    for (int i = 0; i < 4; i++)
        if (e0 + i < E)
            red_add_v4(agg + (size_t)d[i] * H + lane * 4, v[i]);
}

// ---------------- prefill: agg = h_prev (so scatter accumulates h + sum) -----
__global__ void prefill_kernel(const float* __restrict__ src, int lds,
                               float* __restrict__ dst, int N)
{
    int t = blockIdx.x * blockDim.x + threadIdx.x;
    if (t >= N * 32) return;
    int n = t >> 5, c = t & 31;
    reinterpret_cast<float4*>(dst)[(size_t)n * 32 + c] =
        *reinterpret_cast<const float4*>(src + (size_t)n * lds + c * 4);
}

// ---------------- fused GIN MLP (layers 1,2): cp.async pipelined ----------------
// C = relu(relu(A@W1+b1)@W2+b2), A = agg (h preadded), row stride H.
// Thread (tx,ty): rows ty*8..+7, cols {tx*4..+3, 64+tx*4..+3}.
// smem: z_s[128*128] | As0,As1[128*AS_STRIDE] | Bs0,Bs1[16*128]
__global__ void __launch_bounds__(256, 2)
fused_mlp_kernel(const float* __restrict__ A,
                 const float* __restrict__ B1, const float* __restrict__ b1,
                 const float* __restrict__ B2, const float* __restrict__ b2,
                 float* __restrict__ C, int ldC, int N)
{
    extern __shared__ float sm[];
    float* z_s = sm;                            // 128 x 128
    float* As[2] = { sm + 128 * 128, sm + 128 * 128 + 128 * AS_STRIDE };
    float* Bs[2] = { As[1] + 128 * AS_STRIDE, As[1] + 128 * AS_STRIDE + 16 * 128 };

    int tid = threadIdx.x;
    int tx = tid & 15, ty = tid >> 4;
    int m0 = blockIdx.x * 128;

    uint32_t sbase = smem_to_u32(sm);
    uint32_t as_u[2], bs_u[2];
    as_u[0] = sbase + 128 * 128 * 4;
    as_u[1] = as_u[0] + 128 * AS_STRIDE * 4;
    bs_u[0] = as_u[1] + 128 * AS_STRIDE * 4;
    bs_u[1] = bs_u[0] + 16 * 128 * 4;

    // stage A tile t (row-major copy): 512 x 16B chunks, 2 per thread
    auto stageA = [&](int t, int buf) {
        #pragma unroll
        for (int u = 0; u < 2; u++) {
            int i = tid + u * 256;
            int row = i >> 2, c = i & 3;
            cpa16(as_u[buf] + (uint32_t)(row * AS_STRIDE + c * 4) * 4,
                  A + (size_t)(m0 + row) * H + t * 16 + c * 4);
        }
    };
    // stage B tile t from Bsrc: 512 x 16B chunks
    auto stageB = [&](const float* Bsrc, int t, int buf) {
        #pragma unroll
        for (int u = 0; u < 2; u++) {
            int i = tid + u * 256;
            int kr = i >> 5, c = i & 31;
            cpa16(bs_u[buf] + (uint32_t)(kr * 128 + c * 4) * 4,
                  Bsrc + (size_t)(t * 16 + kr) * H + c * 4);
        }
    };

    // ---- phase 1: z = relu(A @ B1 + b1) ----
    stageA(0, 0); stageB(B1, 0, 0); CP_COMMIT();

    ull acc[8][4];
    #pragma unroll
    for (int i = 0; i < 8; i++)
        #pragma unroll
        for (int j = 0; j < 4; j++) acc[i][j] = 0ULL;

    #pragma unroll 1
    for (int t = 0; t < 8; t++) {
        CP_WAIT0();
        __syncthreads();
        if (t < 7) { stageA(t + 1, (t + 1) & 1); stageB(B1, t + 1, (t + 1) & 1); CP_COMMIT(); }
        const float* Ac = As[t & 1];
        const float* Bc = Bs[t & 1];
        #pragma unroll
        for (int kc = 0; kc < 16; kc += 4) {
            float4 rav[8];
            #pragma unroll
            for (int i = 0; i < 8; i++)
                rav[i] = *reinterpret_cast<const float4*>(&Ac[(ty * 8 + i) * AS_STRIDE + kc]);
            #pragma unroll
            for (int k4 = 0; k4 < 4; k4++) {
                int kr = kc + k4;
                ulonglong2 bp0 = *reinterpret_cast<const ulonglong2*>(&Bc[kr * 128 + tx * 4]);
                ulonglong2 bp1 = *reinterpret_cast<const ulonglong2*>(&Bc[kr * 128 + 64 + tx * 4]);
                ull bb[4] = {bp0.x, bp0.y, bp1.x, bp1.y};
                ull ad[8];
                #pragma unroll
                for (int i = 0; i < 8; i++) ad[i] = pkdup(f4c(rav[i], k4));
                #pragma unroll
                for (int i = 0; i < 8; i++)
                    #pragma unroll
                    for (int j = 0; j < 4; j++) ffma2(acc[i][j], ad[i], bb[j]);
            }
        }
    }

    // prefetch B2 tile 0 (Bs0 free: last read compute(6), synced at t=7)
    stageB(B2, 0, 0); CP_COMMIT();

    // epilogue 1: bias + relu -> z_s row-major
    #pragma unroll
    for (int i = 0; i < 8; i++) {
        int r = ty * 8 + i;
        #pragma unroll
        for (int hlf = 0; hlf < 2; hlf++) {
            int j0 = hlf * 64 + tx * 4;
            float2 p0 = unpk(acc[i][hlf * 2 + 0]);
            float2 p1 = unpk(acc[i][hlf * 2 + 1]);
            float4 o;
            o.x = fmaxf(p0.x + b1[j0 + 0], 0.f);
            o.y = fmaxf(p0.y + b1[j0 + 1], 0.f);
            o.z = fmaxf(p1.x + b1[j0 + 2], 0.f);
            o.w = fmaxf(p1.y + b1[j0 + 3], 0.f);
            *reinterpret_cast<float4*>(&z_s[r * 128 + j0]) = o;
        }
    }

    // ---- phase 2: C = relu(z @ B2 + b2) ----
    ull acc2[8][4];
    #pragma unroll
    for (int i = 0; i < 8; i++)
        #pragma unroll
        for (int j = 0; j < 4; j++) acc2[i][j] = 0ULL;

    #pragma unroll 1
    for (int t = 0; t < 8; t++) {
        CP_WAIT0();
        __syncthreads();              // first iter also publishes z_s
        if (t < 7) { stageB(B2, t + 1, (t + 1) & 1); CP_COMMIT(); }
        const float* Bc = Bs[t & 1];
        int kb = t * 16;
        #pragma unroll
        for (int kc = 0; kc < 16; kc += 4) {
            float4 rav[8];
            #pragma unroll
            for (int i = 0; i < 8; i++)
                rav[i] = *reinterpret_cast<const float4*>(&z_s[(ty * 8 + i) * 128 + kb + kc]);
            #pragma unroll
            for (int k4 = 0; k4 < 4; k4++) {
                int kr = kc + k4;
                ulonglong2 bp0 = *reinterpret_cast<const ulonglong2*>(&Bc[kr * 128 + tx * 4]);
                ulonglong2 bp1 = *reinterpret_cast<const ulonglong2*>(&Bc[kr * 128 + 64 + tx * 4]);
                ull bb[4] = {bp0.x, bp0.y, bp1.x, bp1.y};
                ull ad[8];
                #pragma unroll
                for (int i = 0; i < 8; i++) ad[i] = pkdup(f4c(rav[i], k4));
                #pragma unroll
                for (int i = 0; i < 8; i++)
                    #pragma unroll
                    for (int j = 0; j < 4; j++) ffma2(acc2[i][j], ad[i], bb[j]);
            }
        }
    }

    // epilogue 2: bias + relu -> C
    #pragma unroll
    for (int i = 0; i < 8; i++) {
        int gr = m0 + ty * 8 + i;
        if (gr < N) {
            #pragma unroll
            for (int hlf = 0; hlf < 2; hlf++) {
                int j0 = hlf * 64 + tx * 4;
                float2 p0 = unpk(acc2[i][hlf * 2 + 0]);
                float2 p1 = unpk(acc2[i][hlf * 2 + 1]);
                float4 o;
                o.x = fmaxf(p0.x + b2[j0 + 0], 0.f);
                o.y = fmaxf(p0.y + b2[j0 + 1], 0.f);
                o.z = fmaxf(p1.x + b2[j0 + 2], 0.f);
                o.w = fmaxf(p1.y + b2[j0 + 3], 0.f);
                *reinterpret_cast<float4*>(C + (size_t)gr * ldC + j0) = o;
            }
        }
    }
}

// ---------------- fused layer-0 MLP: K1 = 7 (R9-proven, unchanged) -----------
// smem: z_s[128*LDP] | in_s[128*8] | Bs[16*LDP]
__global__ void __launch_bounds__(256, 2)
fused_l0_kernel(const float* __restrict__ x,
                const float* __restrict__ agg7,
                const float* __restrict__ B1, const float* __restrict__ b1,
                const float* __restrict__ B2, const float* __restrict__ b2,
                float* __restrict__ C, int ldC, int N)
{
    extern __shared__ float sm[];
    float* z_s  = sm;                     // 128 x LDP
    float* in_s = sm + 128 * LDP;         // 128 x 8
    float* Bs   = in_s + 1024;            // 16 x LDP

    int tid = threadIdx.x;
    int tx = tid & 15, ty = tid >> 4;
    int m0 = blockIdx.x * 128;

    for (int i = tid; i < 128 * IN_FEAT; i += 256) {
        int r = i / IN_FEAT, k = i % IN_FEAT;
        int gr = m0 + r;
        in_s[r * 8 + k] = (gr < N)
            ? x[(size_t)gr * IN_FEAT + k] + agg7[(size_t)gr * 8 + k] : 0.f;
    }
    for (int i = tid; i < IN_FEAT * H; i += 256) {
        int kr = i >> 7, c = i & 127;
        Bs[kr * LDP + c] = B1[i];
    }
    __syncthreads();

    ull acc[8][4];
    #pragma unroll
    for (int i = 0; i < 8; i++)
        #pragma unroll
        for (int j = 0; j < 4; j++) acc[i][j] = 0ULL;

    #pragma unroll
    for (int k = 0; k < IN_FEAT; k++) {
        ulonglong2 bp0 = *reinterpret_cast<const ulonglong2*>(&Bs[k * LDP + tx * 4]);
        ulonglong2 bp1 = *reinterpret_cast<const ulonglong2*>(&Bs[k * LDP + 64 + tx * 4]);
        ull bb[4] = {bp0.x, bp0.y, bp1.x, bp1.y};
        ull ad[8];
        #pragma unroll
        for (int i = 0; i < 8; i++) ad[i] = pkdup(in_s[(ty * 8 + i) * 8 + k]);
        #pragma unroll
        for (int i = 0; i < 8; i++)
            #pragma unroll
            for (int j = 0; j < 4; j++) ffma2(acc[i][j], ad[i], bb[j]);
    }

    #pragma unroll
    for (int i = 0; i < 8; i++) {
        int r = ty * 8 + i;
        #pragma unroll
        for (int hlf = 0; hlf < 2; hlf++) {
            int j0 = hlf * 64 + tx * 4;
            float2 p0 = unpk(acc[i][hlf * 2 + 0]);
            float2 p1 = unpk(acc[i][hlf * 2 + 1]);
            float4 o;
            o.x = fmaxf(p0.x + b1[j0 + 0], 0.f);
            o.y = fmaxf(p0.y + b1[j0 + 1], 0.f);
            o.z = fmaxf(p1.x + b1[j0 + 2], 0.f);
            o.w = fmaxf(p1.y + b1[j0 + 3], 0.f);
            *reinterpret_cast<float4*>(&z_s[r * LDP + j0]) = o;
        }
    }
    __syncthreads();

    ull acc2[8][4];
    #pragma unroll
    for (int i = 0; i < 8; i++)
        #pragma unroll
        for (int j = 0; j < 4; j++) acc2[i][j] = 0ULL;

    for (int kt = 0; kt < H; kt += 16) {
        #pragma unroll
        for (int u = 0; u < 2; u++) {
            int i = tid + u * 256;
            int kr = i >> 5;
            int c4 = (i & 31) * 4;
            *reinterpret_cast<float4*>(&Bs[kr * LDP + c4]) =
                *reinterpret_cast<const float4*>(B2 + (size_t)(kt + kr) * H + c4);
        }
        __syncthreads();
        #pragma unroll
        for (int kc = 0; kc < 16; kc += 4) {
            float4 rav[8];
            #pragma unroll
            for (int i = 0; i < 8; i++)
                rav[i] = *reinterpret_cast<const float4*>(&z_s[(ty * 8 + i) * LDP + kt + kc]);
            #pragma unroll
            for (int k4 = 0; k4 < 4; k4++) {
                int kr = kc + k4;
                ulonglong2 bp0 = *reinterpret_cast<const ulonglong2*>(&Bs[kr * LDP + tx * 4]);
                ulonglong2 bp1 = *reinterpret_cast<const ulonglong2*>(&Bs[kr * LDP + 64 + tx * 4]);
                ull bb[4] = {bp0.x, bp0.y, bp1.x, bp1.y};
                ull ad[8];
                #pragma unroll
                for (int i = 0; i < 8; i++) ad[i] = pkdup(f4c(rav[i], k4));
                #pragma unroll
                for (int i = 0; i < 8; i++)
                    #pragma unroll
                    for (int j = 0; j < 4; j++) ffma2(acc2[i][j], ad[i], bb[j]);
            }
        }
        __syncthreads();
    }

    #pragma unroll
    for (int i = 0; i < 8; i++) {
        int gr = m0 + ty * 8 + i;
        if (gr < N) {
            #pragma unroll
            for (int hlf = 0; hlf < 2; hlf++) {
                int j0 = hlf * 64 + tx * 4;
                float2 p0 = unpk(acc2[i][hlf * 2 + 0]);
                float2 p1 = unpk(acc2[i][hlf * 2 + 1]);
                float4 o;
                o.x = fmaxf(p0.x + b2[j0 + 0], 0.f);
                o.y = fmaxf(p0.y + b2[j0 + 1], 0.f);
                o.z = fmaxf(p1.x + b2[j0 + 2], 0.f);
                o.w = fmaxf(p1.y + b2[j0 + 3], 0.f);
                *reinterpret_cast<float4*>(C + (size_t)gr * ldC + j0) = o;
            }
        }
    }
}

// ---------------- global add pool over batch ids ----------------
__global__ void pool_kernel(const float* __restrict__ cat,
                            const int* __restrict__ batch,
                            float* __restrict__ pool, int N)
{
    int t = blockIdx.x * blockDim.x + threadIdx.x;
    int total = N * 96;
    if (t >= total) return;
    int n = t / 96;
    int q = t % 96;
    int g = batch[n];
    float4 v = reinterpret_cast<const float4*>(cat)[(size_t)n * 96 + q];
    red_add_v4(pool + (size_t)g * 384 + q * 4, v);
}

// ---------------- classifier layer 1: 384 -> 256 + BN + relu ----------------
__global__ void clf1_kernel(const float* __restrict__ pool,
                            const float* __restrict__ w,
                            const float* __restrict__ b,
                            const float* __restrict__ gamma,
                            const float* __restrict__ beta,
                            const float* __restrict__ mean,
                            const float* __restrict__ var,
                            float* __restrict__ hid)
{
    __shared__ float sp[384];
    int g = blockIdx.x;
    int j = threadIdx.x;                 // 256
    for (int i = j; i < 384; i += 256) sp[i] = pool[(size_t)g * 384 + i];
    __syncthreads();
    float acc = b[j];
    #pragma unroll 8
    for (int k = 0; k < 384; k++) acc += sp[k] * __ldg(w + (size_t)k * 256 + j);
    acc = (acc - mean[j]) * rsqrtf(var[j] + BN_EPS) * gamma[j] + beta[j];
    hid[(size_t)g * 256 + j] = fmaxf(acc, 0.f);
}

// ---------------- classifier layer 2: 256 -> 2 ----------------
__global__ void clf2_kernel(const float* __restrict__ hid,
                            const float* __restrict__ w,
                            const float* __restrict__ b,
                            float* __restrict__ out)
{
    int t = blockIdx.x * blockDim.x + threadIdx.x;
    if (t >= NUM_GRAPHS * 2) return;
    int g = t >> 1, j = t & 1;
    float acc = b[j];
    const float* hr = hid + (size_t)g * 256;
    #pragma unroll 8
    for (int k = 0; k < 256; k++) acc += hr[k] * __ldg(w + k * 2 + j);
    out[t] = acc;
}

// ---------------- launch ----------------
extern "C" void kernel_launch(void* const* d_in, const int* in_sizes, int n_in,
                              void* d_out, int out_size)
{
    const float* x      = (const float*)d_in[0];
    const int*   ei     = (const int*)d_in[1];
    const int*   batch  = (const int*)d_in[2];
    const float* w1[3], *b1[3], *w2[3], *b2[3];
    for (int l = 0; l < 3; l++) {
        w1[l] = (const float*)d_in[3 + 4 * l + 0];
        b1[l] = (const float*)d_in[3 + 4 * l + 1];
        w2[l] = (const float*)d_in[3 + 4 * l + 2];
        b2[l] = (const float*)d_in[3 + 4 * l + 3];
    }
    const float* clf_w1 = (const float*)d_in[15];
    const float* clf_b1 = (const float*)d_in[16];
    const float* clf_w2 = (const float*)d_in[17];
    const float* clf_b2 = (const float*)d_in[18];
    const float* bn_g   = (const float*)d_in[19];
    const float* bn_b   = (const float*)d_in[20];
    const float* bn_m   = (const float*)d_in[21];
    const float* bn_v   = (const float*)d_in[22];
    float* out = (float*)d_out;

    const int N = in_sizes[0] / IN_FEAT;     // 100000
    const int E = in_sizes[1] / 2;           // 1600000

    float *d_agg, *d_cat, *d_pool, *d_hid;
    cudaGetSymbolAddress((void**)&d_agg, g_agg);
    cudaGetSymbolAddress((void**)&d_cat, g_cat);
    cudaGetSymbolAddress((void**)&d_pool, g_pool);
    cudaGetSymbolAddress((void**)&d_hid, g_hid);

    const int* src = ei;
    const int* dst = ei + E;

    const int gemm_blocks = (N + 127) / 128;
    const int SMEM_MLP = (128 * 128 + 2 * 128 * AS_STRIDE + 2 * 16 * 128) * 4;  // 102400
    const int SMEM_L0  = (128 * LDP + 1024 + 16 * LDP) * 4;                      // 80128
    cudaFuncSetAttribute(fused_mlp_kernel, cudaFuncAttributeMaxDynamicSharedMemorySize, SMEM_MLP);
    cudaFuncSetAttribute(fused_l0_kernel,  cudaFuncAttributeMaxDynamicSharedMemorySize, SMEM_L0);

    // ---- layer 0 ----
    cudaMemsetAsync(d_agg, 0, (size_t)N * 8 * sizeof(float));
    scatter7_kernel<<<(E + 255) / 256, 256>>>(x, src, dst, d_agg, E);
    fused_l0_kernel<<<gemm_blocks, 256, SMEM_L0>>>(x, d_agg, w1[0], b1[0],
                                                   w2[0], b2[0], d_cat, 3 * H, N);

    // ---- layers 1, 2 ----
    for (int l = 1; l < 3; l++) {
        const float* h_prev = d_cat + (size_t)(l - 1) * H;  // row stride 384
        // agg <- h_prev, then scatter accumulates: agg = h + sum_neighbors
        prefill_kernel<<<(N * 32 + 255) / 256, 256>>>(h_prev, 3 * H, d_agg, N);
        int warps = (E + 3) / 4;
        scatter128_kernel<<<(warps * 32 + 255) / 256, 256>>>(h_prev, 3 * H, src, dst, d_agg, E);
        fused_mlp_kernel<<<gemm_blocks, 256, SMEM_MLP>>>(d_agg,
                                                         w1[l], b1[l], w2[l], b2[l],
                                                         d_cat + (size_t)l * H, 3 * H, N);
    }

    // ---- global add pool ----
    cudaMemsetAsync(d_pool, 0, (size_t)NUM_GRAPHS * 384 * sizeof(float));
    pool_kernel<<<(N * 96 + 255) / 256, 256>>>(d_cat, batch, d_pool, N);

    // ---- classifier ----
    clf1_kernel<<<NUM_GRAPHS, 256>>>(d_pool, clf_w1, clf_b1, bn_g, bn_b, bn_m, bn_v, d_hid);
    clf2_kernel<<<(NUM_GRAPHS * 2 + 255) / 256, 256>>>(d_hid, clf_w2, clf_b2, out);
}

// round 16
// speedup vs baseline: 1.8352x; 1.1991x over previous
#include <cuda_runtime.h>
#include <cuda_bf16.h>
#include <cstdint>

// ---------------- problem constants ----------------
#define N_NODES   100000
#define N_EDGES   1600000
#define NUM_GRAPHS 1024
#define IN_FEAT   7
#define H         128
#define BN_EPS    1e-5f

#define LDP 132        // padded stride for l0 kernel (R9-proven)
#define AS_STRIDE 20   // A-tile smem row stride (16 data + 4 pad floats)
#define CHUNK 1024
#define NCHUNK ((N_NODES + CHUNK - 1) / CHUNK)   // 98

typedef unsigned long long ull;

// ---------------- scratch (device globals, no allocation) ----------------
__device__ __align__(256) float g_agg[(size_t)(N_NODES + 128) * H];  // padded for cp.async OOB
__device__ __align__(256) float g_cat[(size_t)N_NODES * 3 * H];
__device__ __align__(256) float g_pool[(size_t)NUM_GRAPHS * 3 * H];
__device__ __align__(256) float g_hid[(size_t)NUM_GRAPHS * 2 * H];
// CSR-by-dst build
__device__ int g_deg[N_NODES];
__device__ int g_cursor[N_NODES];
__device__ int g_rowstart[N_NODES + 1];
__device__ int g_esrc[N_EDGES];
__device__ int g_chunkoff[NCHUNK];

// ---------------- helpers ----------------
__device__ __forceinline__ void ffma2(ull& d, ull a, ull b) {
    asm("fma.rn.f32x2 %0, %1, %2, %0;" : "+l"(d) : "l"(a), "l"(b));
}
__device__ __forceinline__ ull pkdup(float a) {
    ull r; asm("mov.b64 %0, {%1, %1};" : "=l"(r) : "f"(a)); return r;
}
__device__ __forceinline__ float2 unpk(ull v) {
    float2 r; asm("mov.b64 {%0, %1}, %2;" : "=f"(r.x), "=f"(r.y) : "l"(v)); return r;
}
__device__ __forceinline__ void red_add_v4(float* addr, float4 v) {
    asm volatile("red.global.add.v4.f32 [%0], {%1, %2, %3, %4};"
                 :: "l"(addr), "f"(v.x), "f"(v.y), "f"(v.z), "f"(v.w)
                 : "memory");
}
__device__ __forceinline__ float f4c(const float4& v, int k) {
    return (k == 0) ? v.x : (k == 1) ? v.y : (k == 2) ? v.z : v.w;
}
__device__ __forceinline__ uint32_t smem_to_u32(const void* p) {
    uint32_t a;
    asm("{ .reg .u64 t; cvta.to.shared.u64 t, %1; cvt.u32.u64 %0, t; }" : "=r"(a) : "l"(p));
    return a;
}
__device__ __forceinline__ void cpa16(uint32_t d, const float* s) {
    asm volatile("cp.async.cg.shared.global [%0], [%1], 16;" :: "r"(d), "l"(s));
}
#define CP_COMMIT() asm volatile("cp.async.commit_group;" ::: "memory")
#define CP_WAIT0()  asm volatile("cp.async.wait_group 0;" ::: "memory")

// ---------------- CSR build ----------------
__global__ void hist_kernel(const int* __restrict__ dst, int* __restrict__ deg, int E)
{
    int e = blockIdx.x * blockDim.x + threadIdx.x;
    if (e < E) atomicAdd(&deg[dst[e]], 1);
}

__global__ void scan1_kernel(const int* __restrict__ deg, int* __restrict__ chunkoff, int N)
{
    __shared__ int ss[256];
    int t = threadIdx.x;
    int base = blockIdx.x * CHUNK + t * 4;
    int s = 0;
    #pragma unroll
    for (int i = 0; i < 4; i++) { int idx = base + i; if (idx < N) s += deg[idx]; }
    ss[t] = s; __syncthreads();
    for (int off = 128; off > 0; off >>= 1) {
        if (t < off) ss[t] += ss[t + off];
        __syncthreads();
    }
    if (t == 0) chunkoff[blockIdx.x] = ss[0];
}

__global__ void scan2_kernel(int* __restrict__ chunkoff, int* __restrict__ rowstart,
                             int nchunk, int N)
{
    if (threadIdx.x == 0 && blockIdx.x == 0) {
        int run = 0;
        for (int i = 0; i < nchunk; i++) { int v = chunkoff[i]; chunkoff[i] = run; run += v; }
        rowstart[N] = run;    // == E
    }
}

__global__ void scan3_kernel(const int* __restrict__ deg, const int* __restrict__ chunkoff,
                             int* __restrict__ rowstart, int* __restrict__ cursor, int N)
{
    __shared__ int ss[256];
    int t = threadIdx.x;
    int base = blockIdx.x * CHUNK + t * 4;
    int v[4]; int s = 0;
    #pragma unroll
    for (int i = 0; i < 4; i++) { int idx = base + i; v[i] = (idx < N) ? deg[idx] : 0; s += v[i]; }
    ss[t] = s; __syncthreads();
    for (int off = 1; off < 256; off <<= 1) {
        int u = (t >= off) ? ss[t - off] : 0;
        __syncthreads();
        ss[t] += u;
        __syncthreads();
    }
    int excl = ss[t] - s + chunkoff[blockIdx.x];
    #pragma unroll
    for (int i = 0; i < 4; i++) {
        int idx = base + i;
        if (idx < N) { rowstart[idx] = excl; cursor[idx] = excl; excl += v[i]; }
    }
}

__global__ void fill_kernel(const int* __restrict__ src, const int* __restrict__ dst,
                            int* __restrict__ cursor, int* __restrict__ esrc, int E)
{
    int e = blockIdx.x * blockDim.x + threadIdx.x;
    if (e >= E) return;
    int p = atomicAdd(&cursor[dst[e]], 1);
    esrc[p] = src[e];
}

// ---------------- layer 0: scatter of 7-dim raw features ----------------
__global__ void scatter7_kernel(const float* __restrict__ x,
                                const int* __restrict__ src,
                                const int* __restrict__ dst,
                                float* __restrict__ agg, int E)
{
    int e = blockIdx.x * blockDim.x + threadIdx.x;
    if (e >= E) return;
    int s = src[e];
    int d = dst[e];
    const float* xr = x + (size_t)s * IN_FEAT;
    float* ar = agg + (size_t)d * 8;
    #pragma unroll
    for (int k = 0; k < IN_FEAT; k++) atomicAdd(ar + k, xr[k]);
}

// ---------------- pull aggregation: agg[d] = h[d] + sum_{s in N(d)} h[s] ------
// one warp per node, lane owns 4 columns; MLP=4 over edges.
__global__ void gather128_kernel(const float* __restrict__ h, int ldH,
                                 const int* __restrict__ rowstart,
                                 const int* __restrict__ esrc,
                                 float* __restrict__ agg, int N)
{
    int node = (blockIdx.x * blockDim.x + threadIdx.x) >> 5;
    int lane = threadIdx.x & 31;
    if (node >= N) return;
    int beg = rowstart[node], end = rowstart[node + 1];

    float4 acc = *reinterpret_cast<const float4*>(h + (size_t)node * ldH + lane * 4);

    int e = beg;
    for (; e + 4 <= end; e += 4) {
        int s0 = __ldg(esrc + e + 0);
        int s1 = __ldg(esrc + e + 1);
        int s2 = __ldg(esrc + e + 2);
        int s3 = __ldg(esrc + e + 3);
        float4 v0 = *reinterpret_cast<const float4*>(h + (size_t)s0 * ldH + lane * 4);
        float4 v1 = *reinterpret_cast<const float4*>(h + (size_t)s1 * ldH + lane * 4);
        float4 v2 = *reinterpret_cast<const float4*>(h + (size_t)s2 * ldH + lane * 4);
        float4 v3 = *reinterpret_cast<const float4*>(h + (size_t)s3 * ldH + lane * 4);
        acc.x += v0.x + v1.x + v2.x + v3.x;
        acc.y += v0.y + v1.y + v2.y + v3.y;
        acc.z += v0.z + v1.z + v2.z + v3.z;
        acc.w += v0.w + v1.w + v2.w + v3.w;
    }
    for (; e < end; e++) {
        int s = __ldg(esrc + e);
        float4 v = *reinterpret_cast<const float4*>(h + (size_t)s * ldH + lane * 4);
        acc.x += v.x; acc.y += v.y; acc.z += v.z; acc.w += v.w;
    }
    *reinterpret_cast<float4*>(agg + (size_t)node * H + lane * 4) = acc;
}

// ---------------- fused GIN MLP (layers 1,2): cp.async pipelined (R14) --------
__global__ void __launch_bounds__(256, 2)
fused_mlp_kernel(const float* __restrict__ A,
                 const float* __restrict__ B1, const float* __restrict__ b1,
                 const float* __restrict__ B2, const float* __restrict__ b2,
                 float* __restrict__ C, int ldC, int N)
{
    extern __shared__ float sm[];
    float* z_s = sm;                            // 128 x 128
    float* As[2] = { sm + 128 * 128, sm + 128 * 128 + 128 * AS_STRIDE };
    float* Bs[2] = { As[1] + 128 * AS_STRIDE, As[1] + 128 * AS_STRIDE + 16 * 128 };

    int tid = threadIdx.x;
    int tx = tid & 15, ty = tid >> 4;
    int m0 = blockIdx.x * 128;

    uint32_t sbase = smem_to_u32(sm);
    uint32_t as_u[2], bs_u[2];
    as_u[0] = sbase + 128 * 128 * 4;
    as_u[1] = as_u[0] + 128 * AS_STRIDE * 4;
    bs_u[0] = as_u[1] + 128 * AS_STRIDE * 4;
    bs_u[1] = bs_u[0] + 16 * 128 * 4;

    auto stageA = [&](int t, int buf) {
        #pragma unroll
        for (int u = 0; u < 2; u++) {
            int i = tid + u * 256;
            int row = i >> 2, c = i & 3;
            cpa16(as_u[buf] + (uint32_t)(row * AS_STRIDE + c * 4) * 4,
                  A + (size_t)(m0 + row) * H + t * 16 + c * 4);
        }
    };
    auto stageB = [&](const float* Bsrc, int t, int buf) {
        #pragma unroll
        for (int u = 0; u < 2; u++) {
            int i = tid + u * 256;
            int kr = i >> 5, c = i & 31;
            cpa16(bs_u[buf] + (uint32_t)(kr * 128 + c * 4) * 4,
                  Bsrc + (size_t)(t * 16 + kr) * H + c * 4);
        }
    };

    // ---- phase 1: z = relu(A @ B1 + b1) ----
    stageA(0, 0); stageB(B1, 0, 0); CP_COMMIT();

    ull acc[8][4];
    #pragma unroll
    for (int i = 0; i < 8; i++)
        #pragma unroll
        for (int j = 0; j < 4; j++) acc[i][j] = 0ULL;

    #pragma unroll 1
    for (int t = 0; t < 8; t++) {
        CP_WAIT0();
        __syncthreads();
        if (t < 7) { stageA(t + 1, (t + 1) & 1); stageB(B1, t + 1, (t + 1) & 1); CP_COMMIT(); }
        const float* Ac = As[t & 1];
        const float* Bc = Bs[t & 1];
        #pragma unroll
        for (int kc = 0; kc < 16; kc += 4) {
            float4 rav[8];
            #pragma unroll
            for (int i = 0; i < 8; i++)
                rav[i] = *reinterpret_cast<const float4*>(&Ac[(ty * 8 + i) * AS_STRIDE + kc]);
            #pragma unroll
            for (int k4 = 0; k4 < 4; k4++) {
                int kr = kc + k4;
                ulonglong2 bp0 = *reinterpret_cast<const ulonglong2*>(&Bc[kr * 128 + tx * 4]);
                ulonglong2 bp1 = *reinterpret_cast<const ulonglong2*>(&Bc[kr * 128 + 64 + tx * 4]);
                ull bb[4] = {bp0.x, bp0.y, bp1.x, bp1.y};
                ull ad[8];
                #pragma unroll
                for (int i = 0; i < 8; i++) ad[i] = pkdup(f4c(rav[i], k4));
                #pragma unroll
                for (int i = 0; i < 8; i++)
                    #pragma unroll
                    for (int j = 0; j < 4; j++) ffma2(acc[i][j], ad[i], bb[j]);
            }
        }
    }

    stageB(B2, 0, 0); CP_COMMIT();

    // epilogue 1: bias + relu -> z_s row-major
    #pragma unroll
    for (int i = 0; i < 8; i++) {
        int r = ty * 8 + i;
        #pragma unroll
        for (int hlf = 0; hlf < 2; hlf++) {
            int j0 = hlf * 64 + tx * 4;
            float2 p0 = unpk(acc[i][hlf * 2 + 0]);
            float2 p1 = unpk(acc[i][hlf * 2 + 1]);
            float4 o;
            o.x = fmaxf(p0.x + b1[j0 + 0], 0.f);
            o.y = fmaxf(p0.y + b1[j0 + 1], 0.f);
            o.z = fmaxf(p1.x + b1[j0 + 2], 0.f);
            o.w = fmaxf(p1.y + b1[j0 + 3], 0.f);
            *reinterpret_cast<float4*>(&z_s[r * 128 + j0]) = o;
        }
    }

    // ---- phase 2: C = relu(z @ B2 + b2) ----
    ull acc2[8][4];
    #pragma unroll
    for (int i = 0; i < 8; i++)
        #pragma unroll
        for (int j = 0; j < 4; j++) acc2[i][j] = 0ULL;

    #pragma unroll 1
    for (int t = 0; t < 8; t++) {
        CP_WAIT0();
        __syncthreads();
        if (t < 7) { stageB(B2, t + 1, (t + 1) & 1); CP_COMMIT(); }
        const float* Bc = Bs[t & 1];
        int kb = t * 16;
        #pragma unroll
        for (int kc = 0; kc < 16; kc += 4) {
            float4 rav[8];
            #pragma unroll
            for (int i = 0; i < 8; i++)
                rav[i] = *reinterpret_cast<const float4*>(&z_s[(ty * 8 + i) * 128 + kb + kc]);
            #pragma unroll
            for (int k4 = 0; k4 < 4; k4++) {
                int kr = kc + k4;
                ulonglong2 bp0 = *reinterpret_cast<const ulonglong2*>(&Bc[kr * 128 + tx * 4]);
                ulonglong2 bp1 = *reinterpret_cast<const ulonglong2*>(&Bc[kr * 128 + 64 + tx * 4]);
                ull bb[4] = {bp0.x, bp0.y, bp1.x, bp1.y};
                ull ad[8];
                #pragma unroll
                for (int i = 0; i < 8; i++) ad[i] = pkdup(f4c(rav[i], k4));
                #pragma unroll
                for (int i = 0; i < 8; i++)
                    #pragma unroll
                    for (int j = 0; j < 4; j++) ffma2(acc2[i][j], ad[i], bb[j]);
            }
        }
    }

    // epilogue 2: bias + relu -> C
    #pragma unroll
    for (int i = 0; i < 8; i++) {
        int gr = m0 + ty * 8 + i;
        if (gr < N) {
            #pragma unroll
            for (int hlf = 0; hlf < 2; hlf++) {
                int j0 = hlf * 64 + tx * 4;
                float2 p0 = unpk(acc2[i][hlf * 2 + 0]);
                float2 p1 = unpk(acc2[i][hlf * 2 + 1]);
                float4 o;
                o.x = fmaxf(p0.x + b2[j0 + 0], 0.f);
                o.y = fmaxf(p0.y + b2[j0 + 1], 0.f);
                o.z = fmaxf(p1.x + b2[j0 + 2], 0.f);
                o.w = fmaxf(p1.y + b2[j0 + 3], 0.f);
                *reinterpret_cast<float4*>(C + (size_t)gr * ldC + j0) = o;
            }
        }
    }
}

// ---------------- fused layer-0 MLP: K1 = 7 (R9-proven, unchanged) -----------
__global__ void __launch_bounds__(256, 2)
fused_l0_kernel(const float* __restrict__ x,
                const float* __restrict__ agg7,
                const float* __restrict__ B1, const float* __restrict__ b1,
                const float* __restrict__ B2, const float* __restrict__ b2,
                float* __restrict__ C, int ldC, int N)
{
    extern __shared__ float sm[];
    float* z_s  = sm;                     // 128 x LDP
    float* in_s = sm + 128 * LDP;         // 128 x 8
    float* Bs   = in_s + 1024;            // 16 x LDP

    int tid = threadIdx.x;
    int tx = tid & 15, ty = tid >> 4;
    int m0 = blockIdx.x * 128;

    for (int i = tid; i < 128 * IN_FEAT; i += 256) {
        int r = i / IN_FEAT, k = i % IN_FEAT;
        int gr = m0 + r;
        in_s[r * 8 + k] = (gr < N)
            ? x[(size_t)gr * IN_FEAT + k] + agg7[(size_t)gr * 8 + k] : 0.f;
    }
    for (int i = tid; i < IN_FEAT * H; i += 256) {
        int kr = i >> 7, c = i & 127;
        Bs[kr * LDP + c] = B1[i];
    }
    __syncthreads();

    ull acc[8][4];
    #pragma unroll
    for (int i = 0; i < 8; i++)
        #pragma unroll
        for (int j = 0; j < 4; j++) acc[i][j] = 0ULL;

    #pragma unroll
    for (int k = 0; k < IN_FEAT; k++) {
        ulonglong2 bp0 = *reinterpret_cast<const ulonglong2*>(&Bs[k * LDP + tx * 4]);
        ulonglong2 bp1 = *reinterpret_cast<const ulonglong2*>(&Bs[k * LDP + 64 + tx * 4]);
        ull bb[4] = {bp0.x, bp0.y, bp1.x, bp1.y};
        ull ad[8];
        #pragma unroll
        for (int i = 0; i < 8; i++) ad[i] = pkdup(in_s[(ty * 8 + i) * 8 + k]);
        #pragma unroll
        for (int i = 0; i < 8; i++)
            #pragma unroll
            for (int j = 0; j < 4; j++) ffma2(acc[i][j], ad[i], bb[j]);
    }

    #pragma unroll
    for (int i = 0; i < 8; i++) {
        int r = ty * 8 + i;
        #pragma unroll
        for (int hlf = 0; hlf < 2; hlf++) {
            int j0 = hlf * 64 + tx * 4;
            float2 p0 = unpk(acc[i][hlf * 2 + 0]);
            float2 p1 = unpk(acc[i][hlf * 2 + 1]);
            float4 o;
            o.x = fmaxf(p0.x + b1[j0 + 0], 0.f);
            o.y = fmaxf(p0.y + b1[j0 + 1], 0.f);
            o.z = fmaxf(p1.x + b1[j0 + 2], 0.f);
            o.w = fmaxf(p1.y + b1[j0 + 3], 0.f);
            *reinterpret_cast<float4*>(&z_s[r * LDP + j0]) = o;
        }
    }
    __syncthreads();

    ull acc2[8][4];
    #pragma unroll
    for (int i = 0; i < 8; i++)
        #pragma unroll
        for (int j = 0; j < 4; j++) acc2[i][j] = 0ULL;

    for (int kt = 0; kt < H; kt += 16) {
        #pragma unroll
        for (int u = 0; u < 2; u++) {
            int i = tid + u * 256;
            int kr = i >> 5;
            int c4 = (i & 31) * 4;
            *reinterpret_cast<float4*>(&Bs[kr * LDP + c4]) =
                *reinterpret_cast<const float4*>(B2 + (size_t)(kt + kr) * H + c4);
        }
        __syncthreads();
        #pragma unroll
        for (int kc = 0; kc < 16; kc += 4) {
            float4 rav[8];
            #pragma unroll
            for (int i = 0; i < 8; i++)
                rav[i] = *reinterpret_cast<const float4*>(&z_s[(ty * 8 + i) * LDP + kt + kc]);
            #pragma unroll
            for (int k4 = 0; k4 < 4; k4++) {
                int kr = kc + k4;
                ulonglong2 bp0 = *reinterpret_cast<const ulonglong2*>(&Bs[kr * LDP + tx * 4]);
                ulonglong2 bp1 = *reinterpret_cast<const ulonglong2*>(&Bs[kr * LDP + 64 + tx * 4]);
                ull bb[4] = {bp0.x, bp0.y, bp1.x, bp1.y};
                ull ad[8];
                #pragma unroll
                for (int i = 0; i < 8; i++) ad[i] = pkdup(f4c(rav[i], k4));
                #pragma unroll
                for (int i = 0; i < 8; i++)
                    #pragma unroll
                    for (int j = 0; j < 4; j++) ffma2(acc2[i][j], ad[i], bb[j]);
            }
        }
        __syncthreads();
    }

    #pragma unroll
    for (int i = 0; i < 8; i++) {
        int gr = m0 + ty * 8 + i;
        if (gr < N) {
            #pragma unroll
            for (int hlf = 0; hlf < 2; hlf++) {
                int j0 = hlf * 64 + tx * 4;
                float2 p0 = unpk(acc2[i][hlf * 2 + 0]);
                float2 p1 = unpk(acc2[i][hlf * 2 + 1]);
                float4 o;
                o.x = fmaxf(p0.x + b2[j0 + 0], 0.f);
                o.y = fmaxf(p0.y + b2[j0 + 1], 0.f);
                o.z = fmaxf(p1.x + b2[j0 + 2], 0.f);
                o.w = fmaxf(p1.y + b2[j0 + 3], 0.f);
                *reinterpret_cast<float4*>(C + (size_t)gr * ldC + j0) = o;
            }
        }
    }
}

// ---------------- global add pool over batch ids ----------------
__global__ void pool_kernel(const float* __restrict__ cat,
                            const int* __restrict__ batch,
                            float* __restrict__ pool, int N)
{
    int t = blockIdx.x * blockDim.x + threadIdx.x;
    int total = N * 96;
    if (t >= total) return;
    int n = t / 96;
    int q = t % 96;
    int g = batch[n];
    float4 v = reinterpret_cast<const float4*>(cat)[(size_t)n * 96 + q];
    red_add_v4(pool + (size_t)g * 384 + q * 4, v);
}

// ---------------- classifier layer 1: 384 -> 256 + BN + relu ----------------
__global__ void clf1_kernel(const float* __restrict__ pool,
                            const float* __restrict__ w,
                            const float* __restrict__ b,
                            const float* __restrict__ gamma,
                            const float* __restrict__ beta,
                            const float* __restrict__ mean,
                            const float* __restrict__ var,
                            float* __restrict__ hid)
{
    __shared__ float sp[384];
    int g = blockIdx.x;
    int j = threadIdx.x;                 // 256
    for (int i = j; i < 384; i += 256) sp[i] = pool[(size_t)g * 384 + i];
    __syncthreads();
    float acc = b[j];
    #pragma unroll 8
    for (int k = 0; k < 384; k++) acc += sp[k] * __ldg(w + (size_t)k * 256 + j);
    acc = (acc - mean[j]) * rsqrtf(var[j] + BN_EPS) * gamma[j] + beta[j];
    hid[(size_t)g * 256 + j] = fmaxf(acc, 0.f);
}

// ---------------- classifier layer 2: 256 -> 2 ----------------
__global__ void clf2_kernel(const float* __restrict__ hid,
                            const float* __restrict__ w,
                            const float* __restrict__ b,
                            float* __restrict__ out)
{
    int t = blockIdx.x * blockDim.x + threadIdx.x;
    if (t >= NUM_GRAPHS * 2) return;
    int g = t >> 1, j = t & 1;
    float acc = b[j];
    const float* hr = hid + (size_t)g * 256;
    #pragma unroll 8
    for (int k = 0; k < 256; k++) acc += hr[k] * __ldg(w + k * 2 + j);
    out[t] = acc;
}

// ---------------- launch ----------------
extern "C" void kernel_launch(void* const* d_in, const int* in_sizes, int n_in,
                              void* d_out, int out_size)
{
    const float* x      = (const float*)d_in[0];
    const int*   ei     = (const int*)d_in[1];
    const int*   batch  = (const int*)d_in[2];
    const float* w1[3], *b1[3], *w2[3], *b2[3];
    for (int l = 0; l < 3; l++) {
        w1[l] = (const float*)d_in[3 + 4 * l + 0];
        b1[l] = (const float*)d_in[3 + 4 * l + 1];
        w2[l] = (const float*)d_in[3 + 4 * l + 2];
        b2[l] = (const float*)d_in[3 + 4 * l + 3];
    }
    const float* clf_w1 = (const float*)d_in[15];
    const float* clf_b1 = (const float*)d_in[16];
    const float* clf_w2 = (const float*)d_in[17];
    const float* clf_b2 = (const float*)d_in[18];
    const float* bn_g   = (const float*)d_in[19];
    const float* bn_b   = (const float*)d_in[20];
    const float* bn_m   = (const float*)d_in[21];
    const float* bn_v   = (const float*)d_in[22];
    float* out = (float*)d_out;

    const int N = in_sizes[0] / IN_FEAT;     // 100000
    const int E = in_sizes[1] / 2;           // 1600000

    float *d_agg, *d_cat, *d_pool, *d_hid;
    int *d_deg, *d_cursor, *d_rowstart, *d_esrc, *d_chunkoff;
    cudaGetSymbolAddress((void**)&d_agg, g_agg);
    cudaGetSymbolAddress((void**)&d_cat, g_cat);
    cudaGetSymbolAddress((void**)&d_pool, g_pool);
    cudaGetSymbolAddress((void**)&d_hid, g_hid);
    cudaGetSymbolAddress((void**)&d_deg, g_deg);
    cudaGetSymbolAddress((void**)&d_cursor, g_cursor);
    cudaGetSymbolAddress((void**)&d_rowstart, g_rowstart);
    cudaGetSymbolAddress((void**)&d_esrc, g_esrc);
    cudaGetSymbolAddress((void**)&d_chunkoff, g_chunkoff);

    const int* src = ei;
    const int* dst = ei + E;

    const int gemm_blocks = (N + 127) / 128;
    const int SMEM_MLP = (128 * 128 + 2 * 128 * AS_STRIDE + 2 * 16 * 128) * 4;  // 102400
    const int SMEM_L0  = (128 * LDP + 1024 + 16 * LDP) * 4;                      // 80128
    cudaFuncSetAttribute(fused_mlp_kernel, cudaFuncAttributeMaxDynamicSharedMemorySize, SMEM_MLP);
    cudaFuncSetAttribute(fused_l0_kernel,  cudaFuncAttributeMaxDynamicSharedMemorySize, SMEM_L0);

    // ---- CSR-by-dst build (overlaps layer-0 on the same stream order) ----
    cudaMemsetAsync(d_deg, 0, N * sizeof(int));
    hist_kernel<<<(E + 255) / 256, 256>>>(dst, d_deg, E);
    scan1_kernel<<<NCHUNK, 256>>>(d_deg, d_chunkoff, N);
    scan2_kernel<<<1, 32>>>(d_chunkoff, d_rowstart, NCHUNK, N);
    scan3_kernel<<<NCHUNK, 256>>>(d_deg, d_chunkoff, d_rowstart, d_cursor, N);
    fill_kernel<<<(E + 255) / 256, 256>>>(src, dst, d_cursor, d_esrc, E);

    // ---- layer 0 ----
    cudaMemsetAsync(d_agg, 0, (size_t)N * 8 * sizeof(float));
    scatter7_kernel<<<(E + 255) / 256, 256>>>(x, src, dst, d_agg, E);
    fused_l0_kernel<<<gemm_blocks, 256, SMEM_L0>>>(x, d_agg, w1[0], b1[0],
                                                   w2[0], b2[0], d_cat, 3 * H, N);

    // ---- layers 1, 2: pull aggregation + fused MLP ----
    for (int l = 1; l < 3; l++) {
        const float* h_prev = d_cat + (size_t)(l - 1) * H;  // row stride 384
        gather128_kernel<<<(N * 32 + 255) / 256, 256>>>(h_prev, 3 * H,
                                                        d_rowstart, d_esrc, d_agg, N);
        fused_mlp_kernel<<<gemm_blocks, 256, SMEM_MLP>>>(d_agg,
                                                         w1[l], b1[l], w2[l], b2[l],
                                                         d_cat + (size_t)l * H, 3 * H, N);
    }

    // ---- global add pool ----
    cudaMemsetAsync(d_pool, 0, (size_t)NUM_GRAPHS * 384 * sizeof(float));
    pool_kernel<<<(N * 96 + 255) / 256, 256>>>(d_cat, batch, d_pool, N);

    // ---- classifier ----
    clf1_kernel<<<NUM_GRAPHS, 256>>>(d_pool, clf_w1, clf_b1, bn_g, bn_b, bn_m, bn_v, d_hid);
    clf2_kernel<<<(NUM_GRAPHS * 2 + 255) / 256, 256>>>(d_hid, clf_w2, clf_b2, out);
}